// round 3
// baseline (speedup 1.0000x reference)
#include <cuda_runtime.h>
#include <cuda_bf16.h>
#include <cstdint>

// embeddings [B=512, I=128, D=64] fp32
// out[b,i,d] = tanh( emb[b,i,d] * (1/I) * sum_j emb[b,j,d] )
//
// R3: reads via cp.async.bulk (UBLKCP) -> one 32KB tile per CTA into smem.
// Avoids the per-SM L1tex wavefront-queue pileup that bound R1/R2 (both
// showed identical 8.5us with DRAM only 25% despite very different
// occupancy/MLP). Compute from smem (conflict-free LDS.128), values held
// in registers, results stored with coalesced STG.128.

static constexpr int BATCH       = 512;
static constexpr int SEQ_I       = 128;
static constexpr int DIM         = 64;
static constexpr int F4_PER_BATCH = SEQ_I * DIM / 4;   // 2048
static constexpr int THREADS      = 256;
static constexpr int F4_PER_THREAD = F4_PER_BATCH / THREADS;  // 8
static constexpr unsigned TILE_BYTES = F4_PER_BATCH * 16;     // 32768

__device__ __forceinline__ float fast_tanh(float x) {
    float y;
    asm("tanh.approx.f32 %0, %1;" : "=f"(y) : "f"(x));
    return y;
}

__global__ __launch_bounds__(THREADS, 4)
void ATT0_40707700032104_kernel(const float* __restrict__ in,
                                float4* __restrict__ out) {
    __shared__ alignas(128) float4 tile[F4_PER_BATCH];   // 32 KB
    __shared__ float4 part[THREADS];                     // 4 KB
    __shared__ float4 mean4[16];
    __shared__ alignas(8) uint64_t mbar;

    const int b = blockIdx.x;
    const int t = threadIdx.x;

    const uint32_t tile_s = (uint32_t)__cvta_generic_to_shared(tile);
    const uint32_t mbar_s = (uint32_t)__cvta_generic_to_shared(&mbar);

    // ---- One bulk async copy: global -> shared (32 KB) ----
    if (t == 0) {
        asm volatile("mbarrier.init.shared.b64 [%0], 1;" :: "r"(mbar_s) : "memory");
    }
    __syncthreads();
    if (t == 0) {
        asm volatile("mbarrier.arrive.expect_tx.shared.b64 _, [%0], %1;"
                     :: "r"(mbar_s), "r"(TILE_BYTES) : "memory");
        const float* src = in + (size_t)b * (SEQ_I * DIM);
        asm volatile(
            "cp.async.bulk.shared::cluster.global.mbarrier::complete_tx::bytes "
            "[%0], [%1], %2, [%3];"
            :: "r"(tile_s), "l"(src), "r"(TILE_BYTES), "r"(mbar_s) : "memory");
    }

    // ---- Wait for bulk copy completion (parity 0) ----
    {
        uint32_t done;
        asm volatile(
            "{\n\t"
            ".reg .pred p;\n\t"
            "mbarrier.try_wait.parity.acquire.cta.shared::cta.b64 p, [%1], 0;\n\t"
            "selp.b32 %0, 1, 0, p;\n\t"
            "}"
            : "=r"(done) : "r"(mbar_s) : "memory");
        if (!done) {
            asm volatile(
                "{\n\t"
                ".reg .pred P1;\n\t"
                "WAIT_LOOP_%=:\n\t"
                "mbarrier.try_wait.parity.acquire.cta.shared::cta.b64 P1, [%0], 0, 0x989680;\n\t"
                "@P1 bra.uni WAIT_DONE_%=;\n\t"
                "bra.uni WAIT_LOOP_%=;\n\t"
                "WAIT_DONE_%=:\n\t"
                "}"
                :: "r"(mbar_s) : "memory");
        }
    }

    // ---- Read tile into registers, accumulate per-column partials ----
    // thread t owns f4 indices t + 256k; column group c = t % 16 invariant.
    float4 v[F4_PER_THREAD];
    float4 s = make_float4(0.f, 0.f, 0.f, 0.f);
#pragma unroll
    for (int k = 0; k < F4_PER_THREAD; k++) {
        v[k] = tile[t + THREADS * k];
        s.x += v[k].x; s.y += v[k].y; s.z += v[k].z; s.w += v[k].w;
    }

    // ---- Cross-thread reduce: 16 row-groups per column group ----
    part[t] = s;
    __syncthreads();

    if (t < 16) {
        float4 m = part[t];
#pragma unroll
        for (int r = 1; r < 16; r++) {
            float4 p = part[t + 16 * r];
            m.x += p.x; m.y += p.y; m.z += p.z; m.w += p.w;
        }
        const float inv = 1.0f / (float)SEQ_I;
        m.x *= inv; m.y *= inv; m.z *= inv; m.w *= inv;
        mean4[t] = m;
    }
    __syncthreads();

    const float4 m = mean4[t & 15];

    // ---- Apply tanh(v * mean) from registers, coalesced STG.128 ----
    float4* dst = out + (size_t)b * F4_PER_BATCH;
#pragma unroll
    for (int k = 0; k < F4_PER_THREAD; k++) {
        float4 r;
        r.x = fast_tanh(v[k].x * m.x);
        r.y = fast_tanh(v[k].y * m.y);
        r.z = fast_tanh(v[k].z * m.z);
        r.w = fast_tanh(v[k].w * m.w);
        dst[t + THREADS * k] = r;
    }
}

extern "C" void kernel_launch(void* const* d_in, const int* in_sizes, int n_in,
                              void* d_out, int out_size) {
    const float* in  = (const float*)d_in[0];
    float4*      out = (float4*)d_out;
    ATT0_40707700032104_kernel<<<BATCH, THREADS>>>(in, out);
}